// round 11
// baseline (speedup 1.0000x reference)
#include <cuda_runtime.h>
#include <math.h>

#define BB   8
#define TT   8192
#define DD   256
#define KK   8
#define CC   64
#define LL   (TT / CC)       // 128
#define NSEQ (BB * DD)       // 2048
#define TOUT (TT - KK + 1)   // 8185
#define QD   4               // K2 prefetch depth

#define TSTEP 8                       // steps per smem tile
#define NT    (LL / TSTEP)            // 16 tiles per chunk
#define RING  3                       // pipeline depth
#define TILEB (TSTEP * DD * 4)        // 8192 bytes

typedef unsigned long long ull;

__device__ float g_trans[CC][36][NSEQ];   // 18.9 MB
__device__ float g_entry[CC][KK][NSEQ];   // 4.2 MB

__host__ __device__ constexpr int coff(int j) { return j * 7 - j * (j - 1) / 2; }

// FFMA with immediate 1.0 multiplier (bit-exact a + c).
#define FMAI(d, a, c) \
    asm("fma.rn.f32 %0, %1, 0f3F800000, %2;" : "=f"(d) : "f"(a), "f"(c))

__device__ __forceinline__ float chainmax(float m, float pred, float f)
{
    float t; FMAI(t, pred, f);
    return fmaxf(m, t);
}

// ---- smem staging primitives ----------------------------------------------
__device__ __forceinline__ unsigned smem_u32(const void* p)
{
    unsigned a;
    asm("{ .reg .u64 t; cvta.to.shared.u64 t, %1; cvt.u32.u64 %0, t; }"
        : "=r"(a) : "l"(p));
    return a;
}

#define MBAR_INIT(addr, cnt) \
    asm volatile("mbarrier.init.shared.b64 [%0], %1;" :: "r"(addr), "r"(cnt) : "memory")
#define MBAR_EXPECT_TX(addr, bytes) \
    asm volatile("mbarrier.arrive.expect_tx.shared.b64 _, [%0], %1;" :: "r"(addr), "r"(bytes) : "memory")
#define MBAR_ARRIVE(addr) \
    asm volatile("mbarrier.arrive.shared.b64 _, [%0];" :: "r"(addr) : "memory")
#define BULK_G2S(dst, src, bytes, mbar) \
    asm volatile("cp.async.bulk.shared::cta.global.mbarrier::complete_tx::bytes [%0], [%1], %2, [%3];" \
                 :: "r"(dst), "l"(src), "r"(bytes), "r"(mbar) : "memory")

__device__ __forceinline__ void mbar_wait(unsigned addr, unsigned parity)
{
    asm volatile(
        "{\n\t"
        ".reg .pred P;\n\t"
        "WL_%=:\n\t"
        "mbarrier.try_wait.parity.acquire.cta.shared::cta.b64 P, [%0], %1, 0x989680;\n\t"
        "@P bra.uni WD_%=;\n\t"
        "bra.uni WL_%=;\n\t"
        "WD_%=:\n\t"
        "}" :: "r"(addr), "r"(parity) : "memory");
}

// ---------------------------------------------------------------------------
// K1: column-split transform with cp.async.bulk smem pipeline.
// Paired blocks: role = blockIdx.x & 1 (A: v + cols 3..6; B: cols 0..2).
// Each block stages its chunk's X tile through a depth-3 smem ring.
// ---------------------------------------------------------------------------
__global__ void __launch_bounds__(256) k1_transform(
    const float* __restrict__ X,
    const float* __restrict__ W,
    const float* __restrict__ Bv)
{
    __shared__ __align__(16) float stg[RING][TSTEP * DD];
    __shared__ __align__(8) ull mbars[2 * RING];

    int tid  = threadIdx.x;
    int d    = tid;                       // 0..255
    int role = blockIdx.x & 1;
    int pid  = blockIdx.x >> 1;           // 0 .. BB*(CC-1)-1
    int b = pid & (BB - 1);
    int c = pid >> 3;                     // 0 .. CC-2
    int s = b * DD + d;

    unsigned mb = smem_u32(mbars);
    unsigned sb = smem_u32(stg);
#define FULLB(i)  (mb + (unsigned)(i) * 8u)
#define EMPTYB(i) (mb + (unsigned)(RING + (i)) * 8u)

    if (tid == 0) {
#pragma unroll
        for (int i = 0; i < RING; i++) {
            MBAR_INIT(FULLB(i), 1);
            MBAR_INIT(EMPTYB(i), 256);
        }
    }
    __syncthreads();

    const char* gsrc = (const char*)(X + ((size_t)b * TT + (size_t)c * LL) * DD);
    if (tid == 0) {
#pragma unroll
        for (int p = 0; p < RING; p++) {
            MBAR_EXPECT_TX(FULLB(p), TILEB);
            BULK_G2S(sb + p * TILEB, gsrc + (size_t)p * TILEB, TILEB, FULLB(p));
        }
    }

    const float NI = -INFINITY;
    float wk[KK], bk[KK];
#pragma unroll
    for (int k = 0; k < KK; k++) {
        wk[k] = __ldg(W + k * DD + d);
        bk[k] = __ldg(Bv + k * DD + d);
    }

    if (role == 0) {
        float v[8], m3[4], m4[3], m5[2], m6;
#pragma unroll
        for (int k = 0; k < 8; k++) v[k] = NI;
#pragma unroll
        for (int i = 0; i < 4; i++) m3[i] = NI;
#pragma unroll
        for (int i = 0; i < 3; i++) m4[i] = NI;
        m5[0] = NI; m5[1] = NI; m6 = NI;

#define A_STEP(x) do {                                                   \
        float f[8];                                                      \
        _Pragma("unroll")                                                \
        for (int k = 0; k < 8; k++) f[k] = fmaf((x), wk[k], bk[k]);      \
        _Pragma("unroll")                                                \
        for (int k = 7; k >= 1; k--) v[k] = chainmax(v[k], v[k-1], f[k]); \
        v[0] = fmaxf(v[0], f[0]);                                        \
        m3[3] = chainmax(m3[3], m3[2], f[7]);                            \
        m3[2] = chainmax(m3[2], m3[1], f[6]);                            \
        m3[1] = chainmax(m3[1], m3[0], f[5]);                            \
        m3[0] = fmaxf(m3[0], f[4]);                                      \
        m4[2] = chainmax(m4[2], m4[1], f[7]);                            \
        m4[1] = chainmax(m4[1], m4[0], f[6]);                            \
        m4[0] = fmaxf(m4[0], f[5]);                                      \
        m5[1] = chainmax(m5[1], m5[0], f[7]);                            \
        m5[0] = fmaxf(m5[0], f[6]);                                      \
        m6    = fmaxf(m6, f[7]);                                         \
    } while (0)

#pragma unroll 1
        for (int ti = 0; ti < NT; ti++) {
            int st = ti % RING;
            unsigned ph = (unsigned)((ti / RING) & 1);
            mbar_wait(FULLB(st), ph);
            const float* xt = stg[st];
#pragma unroll
            for (int j = 0; j < TSTEP; j++) { float x = xt[j * DD + d]; A_STEP(x); }
            MBAR_ARRIVE(EMPTYB(st));
            if (tid == 0 && ti + RING < NT) {
                mbar_wait(EMPTYB(st), ph);
                MBAR_EXPECT_TX(FULLB(st), TILEB);
                BULK_G2S(sb + st * TILEB, gsrc + (size_t)(ti + RING) * TILEB,
                         TILEB, FULLB(st));
            }
        }

#pragma unroll
        for (int k = 0; k < 8; k++) g_trans[c][k][s] = v[k];
#pragma unroll
        for (int i = 0; i < 4; i++) g_trans[c][8 + coff(3) + i][s] = m3[i];
#pragma unroll
        for (int i = 0; i < 3; i++) g_trans[c][8 + coff(4) + i][s] = m4[i];
#pragma unroll
        for (int i = 0; i < 2; i++) g_trans[c][8 + coff(5) + i][s] = m5[i];
        g_trans[c][8 + coff(6)][s] = m6;
    } else {
        float m0[7], m1[6], m2[5];
#pragma unroll
        for (int i = 0; i < 7; i++) m0[i] = NI;
#pragma unroll
        for (int i = 0; i < 6; i++) m1[i] = NI;
#pragma unroll
        for (int i = 0; i < 5; i++) m2[i] = NI;

#define B_STEP(x) do {                                                   \
        float f[8];                                                      \
        _Pragma("unroll")                                                \
        for (int k = 1; k < 8; k++) f[k] = fmaf((x), wk[k], bk[k]);      \
        _Pragma("unroll")                                                \
        for (int i = 6; i >= 1; i--) m0[i] = chainmax(m0[i], m0[i-1], f[i+1]); \
        m0[0] = fmaxf(m0[0], f[1]);                                      \
        _Pragma("unroll")                                                \
        for (int i = 5; i >= 1; i--) m1[i] = chainmax(m1[i], m1[i-1], f[i+2]); \
        m1[0] = fmaxf(m1[0], f[2]);                                      \
        _Pragma("unroll")                                                \
        for (int i = 4; i >= 1; i--) m2[i] = chainmax(m2[i], m2[i-1], f[i+3]); \
        m2[0] = fmaxf(m2[0], f[3]);                                      \
    } while (0)

#pragma unroll 1
        for (int ti = 0; ti < NT; ti++) {
            int st = ti % RING;
            unsigned ph = (unsigned)((ti / RING) & 1);
            mbar_wait(FULLB(st), ph);
            const float* xt = stg[st];
#pragma unroll
            for (int j = 0; j < TSTEP; j++) { float x = xt[j * DD + d]; B_STEP(x); }
            MBAR_ARRIVE(EMPTYB(st));
            if (tid == 0 && ti + RING < NT) {
                mbar_wait(EMPTYB(st), ph);
                MBAR_EXPECT_TX(FULLB(st), TILEB);
                BULK_G2S(sb + st * TILEB, gsrc + (size_t)(ti + RING) * TILEB,
                         TILEB, FULLB(st));
            }
        }

#pragma unroll
        for (int i = 0; i < 7; i++) g_trans[c][8 + coff(0) + i][s] = m0[i];
#pragma unroll
        for (int i = 0; i < 6; i++) g_trans[c][8 + coff(1) + i][s] = m1[i];
#pragma unroll
        for (int i = 0; i < 5; i++) g_trans[c][8 + coff(2) + i][s] = m2[i];
    }
}

// ---------------------------------------------------------------------------
// K2: warp-parallel compose (unchanged from R10).
// ---------------------------------------------------------------------------
__global__ void __launch_bounds__(128) k2_compose()
{
    int t = blockIdx.x * blockDim.x + threadIdx.x;   // 0 .. NSEQ*8-1
    int k = t & 7;
    int s = t >> 3;
    int lane = threadIdx.x & 31;
    int gbase = lane & 24;
    const float NI = -INFINITY;

    int em[7];
#pragma unroll
    for (int j = 0; j < 7; j++)
        em[j] = 8 + coff(j) + k - j - 1;

    const float* base = (const float*)g_trans;

    float pl[QD];
    float pm[QD][7];
#pragma unroll
    for (int u = 0; u < QD; u++) {
        int c = u;
        bool ok = (c <= CC - 2);
        pl[u] = ok ? __ldg(base + ((size_t)c * 36 + k) * NSEQ + s) : NI;
#pragma unroll
        for (int j = 0; j < 7; j++)
            pm[u][j] = (ok && j < k)
                ? __ldg(base + ((size_t)c * 36 + em[j]) * NSEQ + s) : NI;
    }

    float v = NI;

    for (int cb = 0; cb < CC; cb += QD) {
#pragma unroll
        for (int u = 0; u < QD; u++) {
            int c = cb + u;
            g_entry[c][k][s] = v;
            if (c == CC - 1) return;

            float vj[8];
#pragma unroll
            for (int j = 0; j < 8; j++)
                vj[j] = __shfl_sync(0xffffffffu, v, gbase + j);

            float nv = fmaxf(pl[u], v);
#pragma unroll
            for (int j = 0; j < 7; j++)
                nv = fmaxf(nv, vj[j] + pm[u][j]);
            v = nv;

            int cn = c + QD;
            bool ok = (cn <= CC - 2);
            pl[u] = ok ? __ldg(base + ((size_t)cn * 36 + k) * NSEQ + s) : NI;
#pragma unroll
            for (int j = 0; j < 7; j++)
                pm[u][j] = (ok && j < k)
                    ? __ldg(base + ((size_t)cn * 36 + em[j]) * NSEQ + s) : NI;
        }
    }
}

// ---------------------------------------------------------------------------
// K3: staged re-scan. One block per (b, chunk); same smem ring as K1.
// ---------------------------------------------------------------------------
__global__ void __launch_bounds__(256) k3_emit(
    const float* __restrict__ X,
    const float* __restrict__ W,
    const float* __restrict__ Bv,
    float* __restrict__ out)
{
    __shared__ __align__(16) float stg[RING][TSTEP * DD];
    __shared__ __align__(8) ull mbars[2 * RING];

    int tid = threadIdx.x;
    int d = tid;
    int b = blockIdx.x & (BB - 1);
    int c = blockIdx.x >> 3;              // 0 .. CC-1
    int s = b * DD + d;

    unsigned mb = smem_u32(mbars);
    unsigned sb = smem_u32(stg);

    if (tid == 0) {
#pragma unroll
        for (int i = 0; i < RING; i++) {
            MBAR_INIT(FULLB(i), 1);
            MBAR_INIT(EMPTYB(i), 256);
        }
    }
    __syncthreads();

    const char* gsrc = (const char*)(X + ((size_t)b * TT + (size_t)c * LL) * DD);
    if (tid == 0) {
#pragma unroll
        for (int p = 0; p < RING; p++) {
            MBAR_EXPECT_TX(FULLB(p), TILEB);
            BULK_G2S(sb + p * TILEB, gsrc + (size_t)p * TILEB, TILEB, FULLB(p));
        }
    }

    float wk[KK], bk[KK];
#pragma unroll
    for (int k = 0; k < KK; k++) {
        wk[k] = __ldg(W + k * DD + d);
        bk[k] = __ldg(Bv + k * DD + d);
    }

    float v[KK];
#pragma unroll
    for (int k = 0; k < KK; k++) v[k] = g_entry[c][k][s];

    // output base: global out position of in-chunk step i is c*LL + i - 7
    float* obase = out + (((size_t)b * TOUT) + (size_t)c * LL - (KK - 1)) * DD + d;
    int cLL = c * LL;

#pragma unroll 1
    for (int ti = 0; ti < NT; ti++) {
        int st = ti % RING;
        unsigned ph = (unsigned)((ti / RING) & 1);
        mbar_wait(FULLB(st), ph);
        const float* xt = stg[st];
#pragma unroll
        for (int j = 0; j < TSTEP; j++) {
            float x = xt[j * DD + d];
            float f[KK];
#pragma unroll
            for (int k = 0; k < KK; k++) f[k] = fmaf(x, wk[k], bk[k]);
#pragma unroll
            for (int k = KK - 1; k >= 1; k--) v[k] = chainmax(v[k], v[k - 1], f[k]);
            v[0] = fmaxf(v[0], f[0]);

            int i = ti * TSTEP + j;
            if (cLL + i >= KK - 1)
                obase[(size_t)i * DD] = v[KK - 1];
        }
        MBAR_ARRIVE(EMPTYB(st));
        if (tid == 0 && ti + RING < NT) {
            mbar_wait(EMPTYB(st), ph);
            MBAR_EXPECT_TX(FULLB(st), TILEB);
            BULK_G2S(sb + st * TILEB, gsrc + (size_t)(ti + RING) * TILEB,
                     TILEB, FULLB(st));
        }
    }
}

// ---------------------------------------------------------------------------
extern "C" void kernel_launch(void* const* d_in, const int* in_sizes, int n_in,
                              void* d_out, int out_size)
{
    const float* X  = (const float*)d_in[0];
    const float* W  = (const float*)d_in[1];
    const float* Bv = (const float*)d_in[2];
    float* out = (float*)d_out;

    k1_transform<<<2 * BB * (CC - 1), 256>>>(X, W, Bv);
    k2_compose<<<(NSEQ * 8) / 128, 128>>>();
    k3_emit<<<BB * CC, 256>>>(X, W, Bv, out);
}

// round 12
// speedup vs baseline: 1.2309x; 1.2309x over previous
#include <cuda_runtime.h>
#include <math.h>

#define BB   8
#define TT   8192
#define DD   256
#define KK   8
#define CC   64
#define LL   (TT / CC)       // 128
#define NSEQ (BB * DD)       // 2048
#define TOUT (TT - KK + 1)   // 8185
#define QD   4               // K2 prefetch depth
#define PFD  16              // L2 prefetch distance (steps)

// Scratch (static __device__ — no allocation). Scalar layout, coalesced in s.
__device__ float g_trans[CC][36][NSEQ];   // 18.9 MB
__device__ float g_entry[CC][KK][NSEQ];   // 4.2 MB

__host__ __device__ constexpr int coff(int j) { return j * 7 - j * (j - 1) / 2; }

// FFMA with immediate 1.0 multiplier (bit-exact a + c).
#define FMAI(d, a, c) \
    asm("fma.rn.f32 %0, %1, 0f3F800000, %2;" : "=f"(d) : "f"(a), "f"(c))

__device__ __forceinline__ float chainmax(float m, float pred, float f)
{
    float t; FMAI(t, pred, f);
    return fmaxf(m, t);
}

#define PREFETCH_L2(p) \
    asm volatile("prefetch.global.L2 [%0];" :: "l"(p))

#define STG_CS(p, v) \
    asm volatile("st.global.cs.f32 [%0], %1;" :: "l"(p), "f"(v) : "memory")

// ---------------------------------------------------------------------------
// K1: column-split transform (two warps per 32 (chunk,seq) pairs):
//   role 0: local vector v[0..7] + matrix cols 3,4,5,6 (18 states)
//   role 1: matrix cols 0,1,2                          (18 states)
// 8-deep register prefetch + 16-step-ahead L2 prefetch.
// ---------------------------------------------------------------------------
__global__ void __launch_bounds__(64) k1_transform(
    const float* __restrict__ X,
    const float* __restrict__ W,
    const float* __restrict__ Bv)
{
    int lane = threadIdx.x & 31;
    int role = threadIdx.x >> 5;
    int pid  = blockIdx.x * 32 + lane;     // 0 .. NSEQ*(CC-1)-1
    int d = pid & (DD - 1);
    int q = pid >> 8;
    int b = q & (BB - 1);
    int c = q >> 3;                        // 0 .. CC-2
    int s = b * DD + d;

    const float NI = -INFINITY;

    float wk[KK], bk[KK];
#pragma unroll
    for (int k = 0; k < KK; k++) {
        wk[k] = __ldg(W + k * DD + d);
        bk[k] = __ldg(Bv + k * DD + d);
    }

    const float* xp = X + ((size_t)b * TT + (size_t)c * LL) * DD + d;

    float xb[8];
#pragma unroll
    for (int j = 0; j < 8; j++) xb[j] = __ldg(xp + (size_t)j * DD);
#pragma unroll
    for (int j = 8; j < PFD; j++) PREFETCH_L2(xp + (size_t)j * DD);
    xp += (size_t)8 * DD;

    if (role == 0) {
        float v[8], m3[4], m4[3], m5[2], m6;
#pragma unroll
        for (int k = 0; k < 8; k++) v[k] = NI;
#pragma unroll
        for (int i = 0; i < 4; i++) m3[i] = NI;
#pragma unroll
        for (int i = 0; i < 3; i++) m4[i] = NI;
        m5[0] = NI; m5[1] = NI; m6 = NI;

#define A_STEP(x) do {                                                   \
        float f[8];                                                      \
        _Pragma("unroll")                                                \
        for (int k = 0; k < 8; k++) f[k] = fmaf((x), wk[k], bk[k]);      \
        _Pragma("unroll")                                                \
        for (int k = 7; k >= 1; k--) v[k] = chainmax(v[k], v[k-1], f[k]); \
        v[0] = fmaxf(v[0], f[0]);                                        \
        m3[3] = chainmax(m3[3], m3[2], f[7]);                            \
        m3[2] = chainmax(m3[2], m3[1], f[6]);                            \
        m3[1] = chainmax(m3[1], m3[0], f[5]);                            \
        m3[0] = fmaxf(m3[0], f[4]);                                      \
        m4[2] = chainmax(m4[2], m4[1], f[7]);                            \
        m4[1] = chainmax(m4[1], m4[0], f[6]);                            \
        m4[0] = fmaxf(m4[0], f[5]);                                      \
        m5[1] = chainmax(m5[1], m5[0], f[7]);                            \
        m5[0] = fmaxf(m5[0], f[6]);                                      \
        m6    = fmaxf(m6, f[7]);                                         \
    } while (0)

        for (int ii = 0; ii < LL - 8; ii += 8) {
#pragma unroll
            for (int j = 0; j < 8; j++) {
                float x = xb[j];
                xb[j] = __ldg(xp + (size_t)j * DD);
                if (ii + 8 + j + (PFD - 8) < LL)
                    PREFETCH_L2(xp + (size_t)(j + PFD - 8) * DD);
                A_STEP(x);
            }
            xp += (size_t)8 * DD;
        }
#pragma unroll
        for (int j = 0; j < 8; j++) A_STEP(xb[j]);

#pragma unroll
        for (int k = 0; k < 8; k++) g_trans[c][k][s] = v[k];
#pragma unroll
        for (int i = 0; i < 4; i++) g_trans[c][8 + coff(3) + i][s] = m3[i];
#pragma unroll
        for (int i = 0; i < 3; i++) g_trans[c][8 + coff(4) + i][s] = m4[i];
#pragma unroll
        for (int i = 0; i < 2; i++) g_trans[c][8 + coff(5) + i][s] = m5[i];
        g_trans[c][8 + coff(6)][s] = m6;
    } else {
        float m0[7], m1[6], m2[5];
#pragma unroll
        for (int i = 0; i < 7; i++) m0[i] = NI;
#pragma unroll
        for (int i = 0; i < 6; i++) m1[i] = NI;
#pragma unroll
        for (int i = 0; i < 5; i++) m2[i] = NI;

#define B_STEP(x) do {                                                   \
        float f[8];                                                      \
        _Pragma("unroll")                                                \
        for (int k = 1; k < 8; k++) f[k] = fmaf((x), wk[k], bk[k]);      \
        _Pragma("unroll")                                                \
        for (int i = 6; i >= 1; i--) m0[i] = chainmax(m0[i], m0[i-1], f[i+1]); \
        m0[0] = fmaxf(m0[0], f[1]);                                      \
        _Pragma("unroll")                                                \
        for (int i = 5; i >= 1; i--) m1[i] = chainmax(m1[i], m1[i-1], f[i+2]); \
        m1[0] = fmaxf(m1[0], f[2]);                                      \
        _Pragma("unroll")                                                \
        for (int i = 4; i >= 1; i--) m2[i] = chainmax(m2[i], m2[i-1], f[i+3]); \
        m2[0] = fmaxf(m2[0], f[3]);                                      \
    } while (0)

        for (int ii = 0; ii < LL - 8; ii += 8) {
#pragma unroll
            for (int j = 0; j < 8; j++) {
                float x = xb[j];
                xb[j] = __ldg(xp + (size_t)j * DD);
                if (ii + 8 + j + (PFD - 8) < LL)
                    PREFETCH_L2(xp + (size_t)(j + PFD - 8) * DD);
                B_STEP(x);
            }
            xp += (size_t)8 * DD;
        }
#pragma unroll
        for (int j = 0; j < 8; j++) B_STEP(xb[j]);

#pragma unroll
        for (int i = 0; i < 7; i++) g_trans[c][8 + coff(0) + i][s] = m0[i];
#pragma unroll
        for (int i = 0; i < 6; i++) g_trans[c][8 + coff(1) + i][s] = m1[i];
#pragma unroll
        for (int i = 0; i < 5; i++) g_trans[c][8 + coff(2) + i][s] = m2[i];
    }
}

// ---------------------------------------------------------------------------
// K2: warp-parallel compose. 8 threads per sequence (thread = state k);
// v broadcast via shfl; depth-QD register prefetch hides L2 latency.
// ---------------------------------------------------------------------------
__global__ void __launch_bounds__(128) k2_compose()
{
    int t = blockIdx.x * blockDim.x + threadIdx.x;   // 0 .. NSEQ*8-1
    int k = t & 7;
    int s = t >> 3;
    int lane = threadIdx.x & 31;
    int gbase = lane & 24;
    const float NI = -INFINITY;

    int em[7];
#pragma unroll
    for (int j = 0; j < 7; j++)
        em[j] = 8 + coff(j) + k - j - 1;   // valid only when j < k

    const float* base = (const float*)g_trans;

    float pl[QD];
    float pm[QD][7];
#pragma unroll
    for (int u = 0; u < QD; u++) {
        int c = u;
        bool ok = (c <= CC - 2);
        pl[u] = ok ? __ldg(base + ((size_t)c * 36 + k) * NSEQ + s) : NI;
#pragma unroll
        for (int j = 0; j < 7; j++)
            pm[u][j] = (ok && j < k)
                ? __ldg(base + ((size_t)c * 36 + em[j]) * NSEQ + s) : NI;
    }

    float v = NI;

    for (int cb = 0; cb < CC; cb += QD) {
#pragma unroll
        for (int u = 0; u < QD; u++) {
            int c = cb + u;
            g_entry[c][k][s] = v;
            if (c == CC - 1) return;

            float vj[8];
#pragma unroll
            for (int j = 0; j < 8; j++)
                vj[j] = __shfl_sync(0xffffffffu, v, gbase + j);

            float nv = fmaxf(pl[u], v);
#pragma unroll
            for (int j = 0; j < 7; j++)
                nv = fmaxf(nv, vj[j] + pm[u][j]);
            v = nv;

            int cn = c + QD;
            bool ok = (cn <= CC - 2);
            pl[u] = ok ? __ldg(base + ((size_t)cn * 36 + k) * NSEQ + s) : NI;
#pragma unroll
            for (int j = 0; j < 7; j++)
                pm[u][j] = (ok && j < k)
                    ? __ldg(base + ((size_t)cn * 36 + em[j]) * NSEQ + s) : NI;
        }
    }
}

// ---------------------------------------------------------------------------
// K3: scalar re-scan, one thread per (chunk, seq); 8-deep x prefetch +
// L2 prefetch; streaming (evict-first) output stores.
// ---------------------------------------------------------------------------
__device__ __forceinline__ void scan_step(float x, const float* wk,
                                          const float* bk, float* v)
{
    float f[KK];
#pragma unroll
    for (int k = 0; k < KK; k++) f[k] = fmaf(x, wk[k], bk[k]);
#pragma unroll
    for (int k = KK - 1; k >= 1; k--) v[k] = chainmax(v[k], v[k - 1], f[k]);
    v[0] = fmaxf(v[0], f[0]);
}

__global__ void __launch_bounds__(128) k3_emit(
    const float* __restrict__ X,
    const float* __restrict__ W,
    const float* __restrict__ Bv,
    float* __restrict__ out)
{
    int tid = blockIdx.x * blockDim.x + threadIdx.x;   // 0 .. NSEQ*CC-1
    int d = tid & (DD - 1);
    int q = tid >> 8;
    int b = q & (BB - 1);
    int c = q >> 3;
    int s = b * DD + d;

    float wk[KK], bk[KK];
#pragma unroll
    for (int k = 0; k < KK; k++) {
        wk[k] = __ldg(W + k * DD + d);
        bk[k] = __ldg(Bv + k * DD + d);
    }

    float v[KK];
#pragma unroll
    for (int k = 0; k < KK; k++) v[k] = g_entry[c][k][s];

    const float* xp = X + ((size_t)b * TT + (size_t)c * LL) * DD + d;

    float xb[8];
#pragma unroll
    for (int j = 0; j < 8; j++) xb[j] = __ldg(xp + (size_t)j * DD);
#pragma unroll
    for (int j = 8; j < PFD; j++) PREFETCH_L2(xp + (size_t)j * DD);
    xp += (size_t)8 * DD;

    if (c == 0) {
        float* ob = out + (size_t)b * TOUT * DD + d;
        for (int ii = 0; ii < LL - 8; ii += 8) {
#pragma unroll
            for (int j = 0; j < 8; j++) {
                float x = xb[j];
                xb[j] = __ldg(xp + (size_t)j * DD);
                if (ii + 8 + j + (PFD - 8) < LL)
                    PREFETCH_L2(xp + (size_t)(j + PFD - 8) * DD);
                scan_step(x, wk, bk, v);
                int i = ii + j;
                if (i >= KK - 1) STG_CS(ob + (size_t)(i - (KK - 1)) * DD, v[KK - 1]);
            }
            xp += (size_t)8 * DD;
        }
#pragma unroll
        for (int j = 0; j < 8; j++) {
            scan_step(xb[j], wk, bk, v);
            STG_CS(ob + (size_t)(LL - 8 + j - (KK - 1)) * DD, v[KK - 1]);
        }
    } else {
        float* op = out + ((size_t)b * TOUT + (size_t)(c * LL - (KK - 1))) * DD + d;
        for (int ii = 0; ii < LL - 8; ii += 8) {
#pragma unroll
            for (int j = 0; j < 8; j++) {
                float x = xb[j];
                xb[j] = __ldg(xp + (size_t)j * DD);
                if (ii + 8 + j + (PFD - 8) < LL)
                    PREFETCH_L2(xp + (size_t)(j + PFD - 8) * DD);
                scan_step(x, wk, bk, v);
                STG_CS(op + (size_t)(ii + j) * DD, v[KK - 1]);
            }
            xp += (size_t)8 * DD;
        }
#pragma unroll
        for (int j = 0; j < 8; j++) {
            scan_step(xb[j], wk, bk, v);
            STG_CS(op + (size_t)(LL - 8 + j) * DD, v[KK - 1]);
        }
    }
}

// ---------------------------------------------------------------------------
extern "C" void kernel_launch(void* const* d_in, const int* in_sizes, int n_in,
                              void* d_out, int out_size)
{
    const float* X  = (const float*)d_in[0];
    const float* W  = (const float*)d_in[1];
    const float* Bv = (const float*)d_in[2];
    float* out = (float*)d_out;

    k1_transform<<<(NSEQ * (CC - 1)) / 32, 64>>>(X, W, Bv);
    k2_compose<<<(NSEQ * 8) / 128, 128>>>();
    k3_emit<<<(NSEQ * CC) / 128, 128>>>(X, W, Bv, out);
}